// round 17
// baseline (speedup 1.0000x reference)
#include <cuda_runtime.h>
#include <math.h>
#include <stdint.h>

#define B_ 4
#define S_ 2048
#define DM 512
#define H_ 8

// Scratch (device globals — no runtime allocation allowed)
__device__ float g_buf[(size_t)B_*S_*DM];
__device__ float g_qp [(size_t)B_*S_*DM];
__device__ float g_kp [(size_t)B_*S_*DM];
__device__ float g_vp [(size_t)B_*S_*DM];
__device__ float g_oh [(size_t)B_*S_*DM];
__device__ float g_psum[(size_t)B_*H_*S_*64];   // per-row exp partial sums (64 slots)

// ---------------- bf16 helpers ----------------
__device__ __forceinline__ uint32_t pack_bf16(float even, float odd) {
    uint32_t r;
    asm("cvt.rn.bf16x2.f32 %0, %1, %2;" : "=r"(r) : "f"(odd), "f"(even));
    return r;
}
__device__ __forceinline__ void split2(float x0, float x1, uint32_t& hp, uint32_t& lp) {
    hp = pack_bf16(x0, x1);
    float h0 = __uint_as_float(hp << 16);
    float h1 = __uint_as_float(hp & 0xFFFF0000u);
    lp = pack_bf16(x0 - h0, x1 - h1);
}
__device__ __forceinline__ void mma16(float* c, uint4 a, uint32_t b0, uint32_t b1) {
    asm("mma.sync.aligned.m16n8k16.row.col.f32.bf16.bf16.f32 "
        "{%0,%1,%2,%3}, {%4,%5,%6,%7}, {%8,%9}, {%0,%1,%2,%3};"
        : "+f"(c[0]), "+f"(c[1]), "+f"(c[2]), "+f"(c[3])
        : "r"(a.x), "r"(a.y), "r"(a.z), "r"(a.w), "r"(b0), "r"(b1));
}
// ---------------- fp16 helpers (av only) ----------------
__device__ __forceinline__ uint32_t pack_f16(float even, float odd) {
    uint32_t r;
    asm("cvt.rn.f16x2.f32 %0, %1, %2;" : "=r"(r) : "f"(odd), "f"(even));
    return r;
}
__device__ __forceinline__ void unpack_f16(uint32_t p, float& e, float& o) {
    asm("{\n\t.reg .b16 lo, hi;\n\tmov.b32 {lo, hi}, %2;\n\t"
        "cvt.f32.f16 %0, lo;\n\tcvt.f32.f16 %1, hi;\n\t}"
        : "=f"(e), "=f"(o) : "r"(p));
}
__device__ __forceinline__ void split2h(float x0, float x1, uint32_t& hp, uint32_t& lp) {
    hp = pack_f16(x0, x1);
    float h0, h1;
    unpack_f16(hp, h0, h1);
    lp = pack_f16(x0 - h0, x1 - h1);
}
__device__ __forceinline__ void mma16h(float* c, uint4 a, uint32_t b0, uint32_t b1) {
    asm("mma.sync.aligned.m16n8k16.row.col.f32.f16.f16.f32 "
        "{%0,%1,%2,%3}, {%4,%5,%6,%7}, {%8,%9}, {%0,%1,%2,%3};"
        : "+f"(c[0]), "+f"(c[1]), "+f"(c[2]), "+f"(c[3])
        : "r"(a.x), "r"(a.y), "r"(a.z), "r"(a.w), "r"(b0), "r"(b1));
}

// =====================================================================
// bf16x3 GEMM core (R13-R15 configuration).
// =====================================================================

__device__ __forceinline__ void loadA4(const float* __restrict__ As, size_t lda,
                                       int tid, float4* fa) {
    #pragma unroll
    for (int i = 0; i < 4; i++) {
        int lin = tid + i * 256;
        fa[i] = *(const float4*)&As[(size_t)(lin >> 3) * lda + ((lin & 7) << 2)];
    }
}
// av P staging: load exp values, normalize by per-row inv, write back to gmem
__device__ __forceinline__ void loadA4_norm(float* As, size_t lda, int tid,
                                            float4* fa, const float* inv_s) {
    #pragma unroll
    for (int i = 0; i < 4; i++) {
        int lin = tid + i * 256;
        int m = lin >> 3;
        size_t off = (size_t)m * lda + ((lin & 7) << 2);
        float4 f = *(const float4*)&As[off];
        float iv = inv_s[m];
        f.x *= iv; f.y *= iv; f.z *= iv; f.w *= iv;
        *(float4*)&As[off] = f;
        fa[i] = f;
    }
}
__device__ __forceinline__ void storeA4(const float4* fa, int tid,
                                        uint32_t* sAh, uint32_t* sAl) {
    #pragma unroll
    for (int i = 0; i < 4; i++) {
        int lin = tid + i * 256;
        int m = lin >> 3, k4 = (lin & 7) << 2;
        int kc = k4 >> 4, mt = m >> 4, halfm = (m >> 3) & 1, g4 = (m & 7) * 4;
        #pragma unroll
        for (int j = 0; j < 2; j++) {
            int lk = (k4 & 15) + 2 * j;
            int idx = ((kc * 8 + mt) * 32 + g4 + ((lk >> 1) & 3)) * 4
                    + halfm + 2 * ((lk >> 3) & 1);
            uint32_t hp, lp;
            if (j == 0) split2(fa[i].x, fa[i].y, hp, lp);
            else        split2(fa[i].z, fa[i].w, hp, lp);
            sAh[idx] = hp;
            sAl[idx] = lp;
        }
    }
}
// A staging, fp16 hi-only (av P tile)
__device__ __forceinline__ void storeA_h(const float4* fa, int tid, uint32_t* sAh) {
    #pragma unroll
    for (int i = 0; i < 4; i++) {
        int lin = tid + i * 256;
        int m = lin >> 3, k4 = (lin & 7) << 2;
        int kc = k4 >> 4, mt = m >> 4, halfm = (m >> 3) & 1, g4 = (m & 7) * 4;
        #pragma unroll
        for (int j = 0; j < 2; j++) {
            int lk = (k4 & 15) + 2 * j;
            int idx = ((kc * 8 + mt) * 32 + g4 + ((lk >> 1) & 3)) * 4
                    + halfm + 2 * ((lk >> 3) & 1);
            sAh[idx] = (j == 0) ? pack_f16(fa[i].x, fa[i].y)
                                : pack_f16(fa[i].z, fa[i].w);
        }
    }
}
__device__ __forceinline__ void loadB2(const float* __restrict__ Bs, size_t ldb,
                                       int tid, float4* fb) {
    #pragma unroll
    for (int i = 0; i < 2; i++) {
        int lin = tid + i * 256;
        fb[i] = *(const float4*)&Bs[(size_t)(lin >> 3) * ldb + ((lin & 7) << 2)];
    }
}
__device__ __forceinline__ void storeB2(const float4* fb, int tid,
                                        uint32_t* sBh, uint32_t* sBl) {
    #pragma unroll
    for (int i = 0; i < 2; i++) {
        int lin = tid + i * 256;
        int n = lin >> 3, k4 = (lin & 7) << 2;
        int kc = k4 >> 4, nt = n >> 4, haln = (n >> 3) & 1, g4 = (n & 7) * 4;
        #pragma unroll
        for (int j = 0; j < 2; j++) {
            int lk = (k4 & 15) + 2 * j;
            int idx = ((kc * 4 + nt) * 32 + g4 + ((lk >> 1) & 3)) * 4
                    + haln * 2 + ((lk >> 3) & 1);
            uint32_t hp, lp;
            if (j == 0) split2(fb[i].x, fb[i].y, hp, lp);
            else        split2(fb[i].z, fb[i].w, hp, lp);
            sBh[idx] = hp;
            sBl[idx] = lp;
        }
    }
}
// V[k][n] transposed staging (fp16 hi/lo)
__device__ __forceinline__ void loadBT(const float* __restrict__ Bs, size_t ldb,
                                       int tid, float4* fb) {
    int k0 = (tid >> 4) * 2, dv4 = (tid & 15) << 2;
    fb[0] = *(const float4*)&Bs[(size_t)k0 * ldb + dv4];
    fb[1] = *(const float4*)&Bs[(size_t)(k0 + 1) * ldb + dv4];
}
__device__ __forceinline__ void storeBT_h(const float4* fb, int tid,
                                          uint32_t* sBh, uint32_t* sBl) {
    int kp = tid >> 4, dv4 = (tid & 15) << 2;
    int k0 = kp * 2;
    int kc = k0 >> 4, lk = k0 & 15;
    int t = (lk >> 1) & 3, reg = (lk >> 3) & 1;
    const float* e = (const float*)&fb[0];
    const float* o = (const float*)&fb[1];
    #pragma unroll
    for (int j = 0; j < 4; j++) {
        int n = dv4 + j;
        int idx = ((kc * 4 + (n >> 4)) * 32 + (n & 7) * 4 + t) * 4
                + ((n >> 3) & 1) * 2 + reg;
        uint32_t hp, lp;
        split2h(e[j], o[j], hp, lp);
        sBh[idx] = hp;
        sBl[idx] = lp;
    }
}

// compute one 32-k chunk, bf16x3 (A: hi@0/lo@2048; B: hi@0/lo@1024)
__device__ __forceinline__ void compute_chunk2(const uint32_t* sA, const uint32_t* sB,
                                               int wm, int wn, int lane,
                                               float acc[2][4][4]) {
    const uint32_t* sAh = sA;
    const uint32_t* sAl = sA + 2048;
    const uint32_t* sBh = sB;
    const uint32_t* sBl = sB + 1024;
    #pragma unroll
    for (int kc = 0; kc < 2; kc++) {
        uint4 Ah[2], Al[2], Bh[2], Bl[2];
        #pragma unroll
        for (int mtl = 0; mtl < 2; mtl++) {
            int idx = ((kc * 8 + wm * 2 + mtl) * 32 + lane) * 4;
            Ah[mtl] = *(const uint4*)&sAh[idx];
            Al[mtl] = *(const uint4*)&sAl[idx];
        }
        #pragma unroll
        for (int p = 0; p < 2; p++) {
            int idx = ((kc * 4 + wn * 2 + p) * 32 + lane) * 4;
            Bh[p] = *(const uint4*)&sBh[idx];
            Bl[p] = *(const uint4*)&sBl[idx];
        }
        #pragma unroll
        for (int mtl = 0; mtl < 2; mtl++) {
            #pragma unroll
            for (int p = 0; p < 2; p++) {
                mma16(acc[mtl][p * 2],     Ah[mtl], Bh[p].x, Bh[p].y);
                mma16(acc[mtl][p * 2],     Ah[mtl], Bl[p].x, Bl[p].y);
                mma16(acc[mtl][p * 2],     Al[mtl], Bh[p].x, Bh[p].y);
                mma16(acc[mtl][p * 2 + 1], Ah[mtl], Bh[p].z, Bh[p].w);
                mma16(acc[mtl][p * 2 + 1], Ah[mtl], Bl[p].z, Bl[p].w);
                mma16(acc[mtl][p * 2 + 1], Al[mtl], Bh[p].z, Bh[p].w);
            }
        }
    }
}
__device__ __forceinline__ void compute_chunk(const uint32_t* buf, int wm, int wn,
                                              int lane, float acc[2][4][4]) {
    compute_chunk2(buf, buf + 4096, wm, wn, lane, acc);
}
// fp16 av chunk: A hi-only @0 (2048); B: Vh@0, Vl@1024
__device__ __forceinline__ void compute_chunk_av(const uint32_t* sA, const uint32_t* sB,
                                                 int wm, int wn, int lane,
                                                 float acc[2][4][4]) {
    const uint32_t* sVh = sB;
    const uint32_t* sVl = sB + 1024;
    #pragma unroll
    for (int kc = 0; kc < 2; kc++) {
        uint4 Ah[2], Bh[2], Bl[2];
        #pragma unroll
        for (int mtl = 0; mtl < 2; mtl++) {
            int idx = ((kc * 8 + wm * 2 + mtl) * 32 + lane) * 4;
            Ah[mtl] = *(const uint4*)&sA[idx];
        }
        #pragma unroll
        for (int p = 0; p < 2; p++) {
            int idx = ((kc * 4 + wn * 2 + p) * 32 + lane) * 4;
            Bh[p] = *(const uint4*)&sVh[idx];
            Bl[p] = *(const uint4*)&sVl[idx];
        }
        #pragma unroll
        for (int mtl = 0; mtl < 2; mtl++) {
            #pragma unroll
            for (int p = 0; p < 2; p++) {
                mma16h(acc[mtl][p * 2],     Ah[mtl], Bh[p].x, Bh[p].y);
                mma16h(acc[mtl][p * 2],     Ah[mtl], Bl[p].x, Bl[p].y);
                mma16h(acc[mtl][p * 2 + 1], Ah[mtl], Bh[p].z, Bh[p].w);
                mma16h(acc[mtl][p * 2 + 1], Ah[mtl], Bl[p].z, Bl[p].w);
            }
        }
    }
}

__device__ __forceinline__ void store_tile(float* __restrict__ Cb, size_t ldc,
                                           int wm, int wn, int lane,
                                           float acc[2][4][4], float scale) {
    int g = lane >> 2, t = lane & 3;
    #pragma unroll
    for (int mtl = 0; mtl < 2; mtl++) {
        #pragma unroll
        for (int nt = 0; nt < 4; nt++) {
            size_t row = (size_t)(wm * 32 + mtl * 16 + g);
            size_t col = (size_t)(wn * 32 + nt * 8 + t * 2);
            float2 v0 = {acc[mtl][nt][0] * scale, acc[mtl][nt][1] * scale};
            float2 v1 = {acc[mtl][nt][2] * scale, acc[mtl][nt][3] * scale};
            *(float2*)&Cb[row * ldc + col] = v0;
            *(float2*)&Cb[(row + 8) * ldc + col] = v1;
        }
    }
}

// scores epilogue: write exp(s/8) and deterministic per-row partial sums.
// slot2 = ((blockIdx.x*8 + skt)*2 + wn); psum row stride 64.
__device__ __forceinline__ void store_tile_exp(float* __restrict__ Cb, size_t ldc,
                                               float* __restrict__ psum, int slot2,
                                               int wm, int wn, int lane,
                                               float acc[2][4][4]) {
    int g = lane >> 2, t = lane & 3;
    #pragma unroll
    for (int mtl = 0; mtl < 2; mtl++) {
        int r0 = wm * 32 + mtl * 16 + g;
        float s0 = 0.f, s1 = 0.f;
        #pragma unroll
        for (int nt = 0; nt < 4; nt++) {
            size_t col = (size_t)(wn * 32 + nt * 8 + t * 2);
            float e0 = __expf(acc[mtl][nt][0] * 0.125f);
            float e1 = __expf(acc[mtl][nt][1] * 0.125f);
            float e2 = __expf(acc[mtl][nt][2] * 0.125f);
            float e3 = __expf(acc[mtl][nt][3] * 0.125f);
            float2 v0 = {e0, e1};
            float2 v1 = {e2, e3};
            *(float2*)&Cb[(size_t)r0 * ldc + col] = v0;
            *(float2*)&Cb[(size_t)(r0 + 8) * ldc + col] = v1;
            s0 += e0 + e1;
            s1 += e2 + e3;
        }
        s0 += __shfl_xor_sync(0xffffffffu, s0, 1);
        s0 += __shfl_xor_sync(0xffffffffu, s0, 2);
        s1 += __shfl_xor_sync(0xffffffffu, s1, 1);
        s1 += __shfl_xor_sync(0xffffffffu, s1, 2);
        if (t == 0) {
            psum[(size_t)r0 * 64 + slot2] = s0;
            psum[(size_t)(r0 + 8) * 64 + slot2] = s1;
        }
    }
}

__device__ __forceinline__ void gemm_core_nn(
    const float* __restrict__ Ab, size_t lda,
    const float* __restrict__ Bb, size_t ldb,
    float* __restrict__ Cb, size_t ldc,
    float scale, int nchunk, uint32_t* sm)
{
    int tid = threadIdx.x, lane = tid & 31, wid = tid >> 5;
    int wm = wid & 3, wn = wid >> 2;
    uint32_t* buf0 = sm;
    uint32_t* buf1 = sm + 6144;

    float4 fa[4], fb[2];
    float acc[2][4][4] = {};

    loadA4(Ab, lda, tid, fa);
    loadB2(Bb, ldb, tid, fb);
    storeA4(fa, tid, buf0, buf0 + 2048);
    storeB2(fb, tid, buf0 + 4096, buf0 + 5120);
    __syncthreads();

    for (int c = 0; c < nchunk; c++) {
        uint32_t* cur = (c & 1) ? buf1 : buf0;
        uint32_t* nxt = (c & 1) ? buf0 : buf1;
        if (c + 1 < nchunk) {
            loadA4(Ab + (c + 1) * 32, lda, tid, fa);
            loadB2(Bb + (c + 1) * 32, ldb, tid, fb);
        }
        compute_chunk(cur, wm, wn, lane, acc);
        if (c + 1 < nchunk) {
            storeA4(fa, tid, nxt, nxt + 2048);
            storeB2(fb, tid, nxt + 4096, nxt + 5120);
        }
        __syncthreads();
    }
    store_tile(Cb, ldc, wm, wn, lane, acc, scale);
}

// ---------------- kernels ----------------
__global__ __launch_bounds__(256) void proj_mma(const float* __restrict__ A,
                                                const float* __restrict__ W,
                                                float* __restrict__ C) {
    extern __shared__ uint32_t sm[];
    gemm_core_nn(A + (size_t)blockIdx.y * 128 * DM, DM,
                 W + (size_t)blockIdx.x * 64 * DM, DM,
                 C + (size_t)blockIdx.y * 128 * DM + blockIdx.x * 64, DM,
                 1.0f, DM / 32, sm);
}

// scores: Q staged once; 8 K-tiles double-buffered; epilogue = exp + psum.
__global__ __launch_bounds__(256) void scores_mma(const float* __restrict__ qp,
                                                  const float* __restrict__ kp,
                                                  float* __restrict__ attn,
                                                  float* __restrict__ psum) {
    extern __shared__ uint32_t sm[];
    uint32_t* sQ = sm;
    uint32_t* kb0 = sm + 8192;
    uint32_t* kb1 = sm + 12288;
    int tid = threadIdx.x, lane = tid & 31, wid = tid >> 5;
    int wm = wid & 3, wn = wid >> 2;
    int bh = blockIdx.z, b = bh >> 3, h = bh & 7;
    size_t sq0 = (size_t)blockIdx.y * 128;
    size_t skg = (size_t)blockIdx.x * 512;
    const float* Qb = qp + ((size_t)b * S_ + sq0) * DM + h * 64;
    const float* Kg = kp + ((size_t)b * S_ + skg) * DM + h * 64;
    float* ps = psum + ((size_t)bh * S_ + sq0) * 64;

    float4 fa[4], fb[2][2];
    loadA4(Qb, DM, tid, fa);
    storeA4(fa, tid, sQ, sQ + 2048);
    loadA4(Qb + 32, DM, tid, fa);
    storeA4(fa, tid, sQ + 4096, sQ + 6144);
    loadB2(Kg, DM, tid, fb[0]);
    loadB2(Kg + 32, DM, tid, fb[1]);
    storeB2(fb[0], tid, kb0, kb0 + 1024);
    storeB2(fb[1], tid, kb0 + 2048, kb0 + 3072);
    __syncthreads();

    for (int skt = 0; skt < 8; skt++) {
        uint32_t* cur = (skt & 1) ? kb1 : kb0;
        uint32_t* nxt = (skt & 1) ? kb0 : kb1;
        if (skt + 1 < 8) {
            const float* Kt = Kg + (size_t)(skt + 1) * 64 * DM;
            loadB2(Kt, DM, tid, fb[0]);
            loadB2(Kt + 32, DM, tid, fb[1]);
        }
        float acc[2][4][4] = {};
        compute_chunk2(sQ,        cur,        wm, wn, lane, acc);
        compute_chunk2(sQ + 4096, cur + 2048, wm, wn, lane, acc);
        if (skt + 1 < 8) {
            storeB2(fb[0], tid, nxt, nxt + 1024);
            storeB2(fb[1], tid, nxt + 2048, nxt + 3072);
        }
        __syncthreads();
        store_tile_exp(attn + ((size_t)bh * S_ + sq0) * S_ + skg + skt * 64, S_,
                       ps, (int)(blockIdx.x * 8 + skt) * 2 + wn,
                       wm, wn, lane, acc);
    }
}

// av: normalizes P during staging (writes normalized attn back), fp16 P x fp16 V hi/lo.
// smem: buffers 8192 u32 (32KB) + inv_s 128 floats.
__global__ __launch_bounds__(256) void av_mma(float* __restrict__ attn,
                                              const float* __restrict__ vp,
                                              float* __restrict__ oh,
                                              const float* __restrict__ psum) {
    extern __shared__ uint32_t sm[];
    uint32_t* buf0 = sm;
    uint32_t* buf1 = sm + 4096;
    float* inv_s = (float*)(sm + 8192);
    int tid = threadIdx.x, lane = tid & 31, wid = tid >> 5;
    int wm = wid & 3, wn = wid >> 2;
    int bh = blockIdx.y, b = bh >> 3, h = bh & 7;
    size_t sq0 = (size_t)blockIdx.x * 128;
    float* Pb = attn + ((size_t)bh * S_ + sq0) * S_;
    const float* Vb = vp + (size_t)b * S_ * DM + h * 64;

    // per-row inverse sums (deterministic: fixed summation order)
    if (tid < 128) {
        const float* pr = psum + ((size_t)bh * S_ + sq0 + tid) * 64;
        float s = 0.f;
        #pragma unroll
        for (int i = 0; i < 64; i++) s += pr[i];
        inv_s[tid] = 1.0f / s;
    }
    __syncthreads();

    float4 fa[4], fb[2];
    float acc[2][4][4] = {};

    loadA4_norm(Pb, S_, tid, fa, inv_s);
    loadBT(Vb, DM, tid, fb);
    storeA_h(fa, tid, buf0);
    storeBT_h(fb, tid, buf0 + 2048, buf0 + 3072);
    __syncthreads();

    const int NC = S_ / 32;   // 64
    for (int c = 0; c < NC; c++) {
        uint32_t* cur = (c & 1) ? buf1 : buf0;
        uint32_t* nxt = (c & 1) ? buf0 : buf1;
        if (c + 1 < NC) {
            loadA4_norm(Pb + (c + 1) * 32, S_, tid, fa, inv_s);
            loadBT(Vb + (size_t)(c + 1) * 32 * DM, DM, tid, fb);
        }
        compute_chunk_av(cur, cur + 2048, wm, wn, lane, acc);
        if (c + 1 < NC) {
            storeA_h(fa, tid, nxt);
            storeBT_h(fb, tid, nxt + 2048, nxt + 3072);
        }
        __syncthreads();
    }
    store_tile(oh + ((size_t)b * S_ + sq0) * DM + h * 64, DM, wm, wn, lane, acc, 1.0f);
}

// ---------------- LayerNorm (shuffle reductions, 2 barriers) ----------------
__global__ void ln_kernel(const float* __restrict__ x, float* __restrict__ y,
                          const float* __restrict__ g, const float* __restrict__ bb) {
    int row = blockIdx.x;
    int t = threadIdx.x, lane = t & 31, wid = t >> 5;
    float2 f = *(const float2*)&x[(size_t)row * DM + 2 * t];
    __shared__ float redm[8], redv[8];
    float s = f.x + f.y;
    #pragma unroll
    for (int o = 16; o; o >>= 1) s += __shfl_xor_sync(0xffffffffu, s, o);
    if (lane == 0) redm[wid] = s;
    __syncthreads();
    float mu = 0.f;
    #pragma unroll
    for (int i = 0; i < 8; i++) mu += redm[i];
    mu *= (1.0f / DM);
    float d0 = f.x - mu, d1 = f.y - mu;
    float vv = d0 * d0 + d1 * d1;
    #pragma unroll
    for (int o = 16; o; o >>= 1) vv += __shfl_xor_sync(0xffffffffu, vv, o);
    if (lane == 0) redv[wid] = vv;
    __syncthreads();
    float var = 0.f;
    #pragma unroll
    for (int i = 0; i < 8; i++) var += redv[i];
    float rstd = rsqrtf(var * (1.0f / DM) + 1e-5f);
    float2 gg = *(const float2*)&g[2 * t];
    float2 bv = *(const float2*)&bb[2 * t];
    float2 out;
    out.x = d0 * rstd * gg.x + bv.x;
    out.y = d1 * rstd * gg.y + bv.y;
    *(float2*)&y[(size_t)row * DM + 2 * t] = out;
}

extern "C" void kernel_launch(void* const* d_in, const int* in_sizes, int n_in,
                              void* d_out, int out_size) {
    const float* q    = (const float*)d_in[0];
    const float* k    = (const float*)d_in[1];
    const float* v    = (const float*)d_in[2];
    const float* W_Q  = (const float*)d_in[3];
    const float* W_K  = (const float*)d_in[4];
    const float* W_V  = (const float*)d_in[5];
    const float* W_fc = (const float*)d_in[6];
    const float* ln_g = (const float*)d_in[7];
    const float* ln_b = (const float*)d_in[8];

    float* out  = (float*)d_out;                       // [B,S,512]
    float* attn = out + (size_t)B_ * S_ * DM;          // [B,H,S,S]

    float *buf, *qp, *kp, *vp, *oh, *psum;
    cudaGetSymbolAddress((void**)&buf,  g_buf);
    cudaGetSymbolAddress((void**)&qp,   g_qp);
    cudaGetSymbolAddress((void**)&kp,   g_kp);
    cudaGetSymbolAddress((void**)&vp,   g_vp);
    cudaGetSymbolAddress((void**)&oh,   g_oh);
    cudaGetSymbolAddress((void**)&psum, g_psum);

    const int SMEM    = 48 * 1024;
    const int SMEM_S  = 64 * 1024;
    const int SMEM_AV = 33 * 1024;
    cudaFuncSetAttribute(proj_mma,   cudaFuncAttributeMaxDynamicSharedMemorySize, SMEM);
    cudaFuncSetAttribute(scores_mma, cudaFuncAttributeMaxDynamicSharedMemorySize, SMEM_S);
    cudaFuncSetAttribute(av_mma,     cudaFuncAttributeMaxDynamicSharedMemorySize, SMEM_AV);

    const int ROWS = B_ * S_;                          // 8192
    dim3 proj_grid(DM / 64, ROWS / 128);               // (8, 64)

    // Q path
    ln_kernel<<<ROWS, 256>>>(q, buf, ln_g, ln_b);
    proj_mma<<<proj_grid, 256, SMEM>>>(buf, W_Q, qp);
    // K path
    ln_kernel<<<ROWS, 256>>>(k, buf, ln_g, ln_b);
    proj_mma<<<proj_grid, 256, SMEM>>>(buf, W_K, kp);
    // V path
    ln_kernel<<<ROWS, 256>>>(v, buf, ln_g, ln_b);
    proj_mma<<<proj_grid, 256, SMEM>>>(buf, W_V, vp);

    // Attention (softmax folded into scores epilogue + av staging)
    scores_mma<<<dim3(S_ / 512, S_ / 128, B_ * H_), 256, SMEM_S>>>(qp, kp, attn, psum);
    av_mma<<<dim3(S_ / 128, B_ * H_), 256, SMEM_AV>>>(attn, vp, oh, psum);

    // Output LN + fc
    ln_kernel<<<ROWS, 256>>>(oh, buf, ln_g, ln_b);
    proj_mma<<<proj_grid, 256, SMEM>>>(buf, W_fc, out);
}